// round 4
// baseline (speedup 1.0000x reference)
#include <cuda_runtime.h>

// Problem constants
#define B_  2
#define E_  16
#define H_  160
#define W_  288
#define N_  12
#define T_  2
#define HW_ (H_ * W_)           // 46080
#define P_  (T_ * HW_)          // 92160 pixels per instance
#define BN_ (B_ * N_)           // 24 instances
#define NE_ (N_ * E_)           // 192
#define NBINS 16384             // error bins over [0, 2]
#define BIN_SCALE 8192.0f       // NBINS / 2
#define NSLOT (BN_ * 2)         // slot = inst*2 + mv
#define BPT 16                  // bins per thread in k_loss (NBINS/1024)

// Scratch (static __device__ arrays — no allocation allowed)
__device__ unsigned int d_hist[NSLOT * NBINS];      // 3.1 MB
__device__ unsigned int d_pack[B_ * P_];            // packed masks, 737 KB
__device__ double       d_S1[BN_ * E_];
__device__ double       d_S2[BN_ * E_];
__device__ unsigned int d_cnt[BN_];
__device__ float        d_mean[BN_ * E_];
__device__ float        d_nhv [BN_ * E_];           // -0.5 * var
__device__ double       d_total;
__device__ unsigned int d_tick1;
__device__ unsigned int d_tick2;

// ---------------------------------------------------------------------------
// Kernel 0: clear histogram + accumulators
// ---------------------------------------------------------------------------
__global__ void k_clear() {
    size_t i = (size_t)blockIdx.x * blockDim.x + threadIdx.x;
    size_t stride = (size_t)gridDim.x * blockDim.x;
    const size_t n4 = (size_t)NSLOT * NBINS / 4;
    uint4 z = make_uint4(0u, 0u, 0u, 0u);
    uint4* h = reinterpret_cast<uint4*>(d_hist);
    for (size_t j = i; j < n4; j += stride) h[j] = z;
    if (i < BN_ * E_) { d_S1[i] = 0.0; d_S2[i] = 0.0; }
    if (i < BN_)      { d_cnt[i] = 0u; }
    if (i == 0)       { d_total = 0.0; d_tick1 = 0u; d_tick2 = 0u; }
}

// ---------------------------------------------------------------------------
// Kernel 1: pack masks + masked sums + (fused) finalize of mean/var.
// grid (64 chunks, B_), block 512.  Chunk of 1440 pixels lies in one frame t.
// ---------------------------------------------------------------------------
__global__ void __launch_bounds__(512) k_stats(const float* __restrict__ mf1,
                                               const float* __restrict__ mf2,
                                               const int*   __restrict__ gt) {
    __shared__ unsigned int spack[P_ / 64];   // 1440
    const int b    = blockIdx.y;
    const int tid  = threadIdx.x;
    const int CPIX = P_ / 64;                 // 1440
    const int p0   = blockIdx.x * CPIX;
    const int t    = p0 / HW_;
    const int hw0  = p0 - t * HW_;

    // Phase 1: pack 12 masks/pixel into one uint32
    const int* g0 = gt + (((size_t)b * N_) * T_ + t) * HW_ + hw0;
    for (int k = tid; k < CPIX; k += 512) {
        unsigned w = 0u;
#pragma unroll
        for (int n = 0; n < N_; n++)
            w |= ((unsigned)g0[(size_t)n * (T_ * HW_) + k]) << n;
        spack[k] = w;
        d_pack[(size_t)b * P_ + p0 + k] = w;
    }
    __syncthreads();

    // Phase 2: accumulate (warp w = embed dim e)
    const int e    = tid >> 5;
    const int lane = tid & 31;
    const float* f = (t == 0 ? mf1 : mf2) + ((size_t)b * E_ + e) * HW_ + hw0;

    float s1[N_], s2[N_];
    int   c[N_];
#pragma unroll
    for (int n = 0; n < N_; n++) { s1[n] = 0.f; s2[n] = 0.f; c[n] = 0; }

    for (int k = lane; k < CPIX; k += 32) {
        float x  = f[k];
        float x2 = x * x;
        unsigned pw = spack[k];
#pragma unroll
        for (int n = 0; n < N_; n++) {
            if ((pw >> n) & 1u) { s1[n] += x; s2[n] += x2; c[n]++; }
        }
    }

#pragma unroll
    for (int n = 0; n < N_; n++) {
        float a  = s1[n];
        float bb = s2[n];
        for (int off = 16; off; off >>= 1) {
            a  += __shfl_down_sync(0xffffffffu, a,  off);
            bb += __shfl_down_sync(0xffffffffu, bb, off);
        }
        if (lane == 0) {
            atomicAdd(&d_S1[((size_t)b * N_ + n) * E_ + e], (double)a);
            atomicAdd(&d_S2[((size_t)b * N_ + n) * E_ + e], (double)bb);
        }
    }
    if (e == 0) {
#pragma unroll
        for (int n = 0; n < N_; n++) {
            int cc = c[n];
            for (int off = 16; off; off >>= 1)
                cc += __shfl_down_sync(0xffffffffu, cc, off);
            if (lane == 0) atomicAdd(&d_cnt[b * N_ + n], (unsigned)cc);
        }
    }

    // Fused finalize (last block)
    __threadfence();
    __shared__ bool isLast;
    if (tid == 0) isLast = (atomicAdd(&d_tick1, 1u) == (unsigned)(64 * B_ - 1));
    __syncthreads();
    if (isLast && tid < BN_ * E_) {
        int inst   = tid / E_;
        double cnt = (double)d_cnt[inst];
        double s1v = d_S1[tid];
        double s2v = d_S2[tid];
        double mean = s1v / cnt;
        double var  = (s2v - s1v * s1v / cnt) / (cnt - 1.0);
        d_mean[tid] = (float)mean;
        d_nhv[tid]  = (float)(-0.5 * var);
    }
}

// ---------------------------------------------------------------------------
// Kernel 2: per-pixel distance -> error -> histogram (warp-aggregated atomics)
// grid 720, block 256. One thread = one pixel (covers both batches).
// ---------------------------------------------------------------------------
__global__ void __launch_bounds__(256) k_hist(const float* __restrict__ mf1,
                                              const float* __restrict__ mf2) {
    __shared__ float sm_mean[NE_];
    __shared__ float sm_nhv [NE_];
    const int tid = threadIdx.x;
    const int b   = (blockIdx.x * 256) / P_;         // uniform in block (P_ % 256 == 0)
    if (tid < NE_) {
        sm_mean[tid] = d_mean[b * NE_ + tid];
        sm_nhv [tid] = d_nhv [b * NE_ + tid];
    }
    __syncthreads();

    const int pp = blockIdx.x * 256 + tid;           // < B_*P_ exactly
    const int p  = pp - b * P_;
    const int t  = p / HW_;
    const int hw = p - t * HW_;
    const int lane = tid & 31;

    const float* f = (t == 0 ? mf1 : mf2) + (size_t)b * E_ * HW_ + hw;
    float x[E_];
#pragma unroll
    for (int e = 0; e < E_; e++) x[e] = f[(size_t)e * HW_];

    const unsigned pw = d_pack[pp];

#pragma unroll
    for (int n = 0; n < N_; n++) {
        float d = 0.f;
#pragma unroll
        for (int e = 0; e < E_; e++) {
            float diff = x[e] - sm_mean[n * E_ + e];
            d = fmaf(diff * diff, sm_nhv[n * E_ + e], d);  // d = -0.5 * sum
        }
        float q   = __expf(d);                       // in (0, 1]
        unsigned mv = (pw >> n) & 1u;
        float err = mv ? (2.0f - 2.0f * q) : (2.0f * q);
        int bin   = (int)(err * BIN_SCALE);
        bin       = bin < (NBINS - 1) ? bin : (NBINS - 1);

        // warp-aggregate identical (mv, bin) pairs -> one atomic per group
        unsigned key   = (mv << 14) | (unsigned)bin;
        unsigned peers = __match_any_sync(0xffffffffu, key);
        int leader     = __ffs(peers) - 1;
        if (lane == leader) {
            int slot = ((b * N_ + n) << 1) | (int)mv;
            atomicAdd(&d_hist[(size_t)slot * NBINS + bin],
                      (unsigned)__popc(peers));
        }
    }
}

// ---------------------------------------------------------------------------
// Kernel 3: full histogram scan + Lovasz contribution + (fused) scalar out.
// One block per instance; 1024 threads x 16 bins = 16384 bins.
// Sorted order is DESCENDING error; with ascending exclusive prefixes:
//   before: cp0 = totPos - (excl + cnt), after: cp1 = totPos - excl
//   J(cp,cn) = 1 - (gts - cp)/(gts + cn);  contrib = e_rep * (J1 - J0)
// ---------------------------------------------------------------------------
__global__ void __launch_bounds__(1024) k_loss(float* __restrict__ out) {
    const int inst = blockIdx.x;
    const int tid  = threadIdx.x;
    const size_t baseN = ((size_t)(inst * 2)     * NBINS) + (size_t)tid * BPT;
    const size_t baseP = ((size_t)(inst * 2 + 1) * NBINS) + (size_t)tid * BPT;

    unsigned cntP[BPT], cntN[BPT];
#pragma unroll
    for (int j = 0; j < BPT; j += 4) {
        uint4 vp = *reinterpret_cast<const uint4*>(&d_hist[baseP + j]);
        uint4 vn = *reinterpret_cast<const uint4*>(&d_hist[baseN + j]);
        cntP[j] = vp.x; cntP[j+1] = vp.y; cntP[j+2] = vp.z; cntP[j+3] = vp.w;
        cntN[j] = vn.x; cntN[j+1] = vn.y; cntN[j+2] = vn.z; cntN[j+3] = vn.w;
    }
    unsigned tp = 0, tn = 0;
#pragma unroll
    for (int j = 0; j < BPT; j++) { tp += cntP[j]; tn += cntN[j]; }

    __shared__ unsigned sp[1024], sn[1024];
    sp[tid] = tp; sn[tid] = tn;
    __syncthreads();
    for (int s = 1; s < 1024; s <<= 1) {
        unsigned vp = (tid >= s) ? sp[tid - s] : 0u;
        unsigned vn = (tid >= s) ? sn[tid - s] : 0u;
        __syncthreads();
        sp[tid] += vp; sn[tid] += vn;
        __syncthreads();
    }
    unsigned runP = sp[tid] - tp;                    // exclusive ascending prefix
    unsigned runN = sn[tid] - tn;

    const double totPos = (double)d_cnt[inst];
    const double totNeg = (double)P_ - totPos;
    const double gts    = totPos;
    const double dbin   = 2.0 / (double)NBINS;

    double acc = 0.0;
#pragma unroll
    for (int j = 0; j < BPT; j++) {
        unsigned cp = cntP[j], cn = cntN[j];
        if (cp | cn) {
            double cp0 = totPos - (double)(runP + cp);
            double cn0 = totNeg - (double)(runN + cn);
            double cp1 = totPos - (double)runP;
            double cn1 = totNeg - (double)runN;
            double J0 = 1.0 - (gts - cp0) / (gts + cn0);
            double J1 = 1.0 - (gts - cp1) / (gts + cn1);
            double e_rep = ((double)(tid * BPT + j) + 0.5) * dbin;
            acc += e_rep * (J1 - J0);
        }
        runP += cp; runN += cn;
    }

    // block reduce of acc
    __shared__ double sd[1024];
    sd[tid] = acc;
    __syncthreads();
    for (int s = 512; s; s >>= 1) {
        if (tid < s) sd[tid] += sd[tid + s];
        __syncthreads();
    }
    if (tid == 0) atomicAdd(&d_total, sd[0]);

    // Fused scalar output (last block)
    __threadfence();
    __shared__ bool isLast;
    if (tid == 0) isLast = (atomicAdd(&d_tick2, 1u) == (unsigned)(BN_ - 1));
    __syncthreads();
    if (isLast && tid == 0) out[0] = (float)(d_total / (double)BN_);
}

extern "C" void kernel_launch(void* const* d_in, const int* in_sizes, int n_in,
                              void* d_out, int out_size) {
    const float* mf1 = (const float*)d_in[0];
    const float* mf2 = (const float*)d_in[1];
    const int*   gt  = (const int*)d_in[2];

    k_clear<<<768, 256>>>();
    k_stats<<<dim3(64, B_), 512>>>(mf1, mf2, gt);
    k_hist<<<(B_ * P_) / 256, 256>>>(mf1, mf2);
    k_loss<<<BN_, 1024>>>((float*)d_out);
}

// round 6
// speedup vs baseline: 2.1786x; 2.1786x over previous
#include <cuda_runtime.h>

// Problem constants
#define B_  2
#define E_  16
#define H_  160
#define W_  288
#define N_  12
#define T_  2
#define HW_ (H_ * W_)           // 46080
#define P_  (T_ * HW_)          // 92160 pixels per instance
#define BN_ (B_ * N_)           // 24 instances
#define NE_ (N_ * E_)           // 192
#define NBINS 16384             // error bins over [0, 2]
#define BIN_SCALE 8192.0f       // NBINS / 2
#define DBINF (2.0f / 16384.0f)
#define NSLOT (BN_ * 2)         // slot = inst*2 + mv
#define BPT 16                  // bins per thread in k_loss (NBINS/1024)

// Scratch (static __device__ arrays — zero-initialized at load; k_loss's last
// block restores the zero state every call, so no clear kernel is needed).
__device__ unsigned int d_hist[NSLOT * NBINS];      // 3.1 MB
__device__ unsigned int d_pack[B_ * P_];            // packed masks, 737 KB
__device__ double       d_S1[BN_ * E_];
__device__ double       d_S2[BN_ * E_];
__device__ unsigned int d_cnt[BN_];
__device__ float        d_mean[BN_ * E_];
__device__ float        d_nhv [BN_ * E_];           // -0.5 * var
__device__ double       d_total;
__device__ unsigned int d_tick1;
__device__ unsigned int d_tick2;

// ---------------------------------------------------------------------------
// Kernel 1: pack masks + masked sums + (fused) finalize of mean/var.
// grid (64 chunks, B_), block 512.  Chunk of 1440 pixels lies in one frame t.
// ---------------------------------------------------------------------------
__global__ void __launch_bounds__(512) k_stats(const float* __restrict__ mf1,
                                               const float* __restrict__ mf2,
                                               const int*   __restrict__ gt) {
    __shared__ unsigned int spack[P_ / 64];   // 1440
    const int b    = blockIdx.y;
    const int tid  = threadIdx.x;
    const int CPIX = P_ / 64;                 // 1440
    const int p0   = blockIdx.x * CPIX;
    const int t    = p0 / HW_;
    const int hw0  = p0 - t * HW_;

    // Phase 1: pack 12 masks/pixel into one uint32
    const int* g0 = gt + (((size_t)b * N_) * T_ + t) * HW_ + hw0;
    for (int k = tid; k < CPIX; k += 512) {
        unsigned w = 0u;
#pragma unroll
        for (int n = 0; n < N_; n++)
            w |= ((unsigned)g0[(size_t)n * (T_ * HW_) + k]) << n;
        spack[k] = w;
        d_pack[(size_t)b * P_ + p0 + k] = w;
    }
    __syncthreads();

    // Phase 2: accumulate (warp w = embed dim e)
    const int e    = tid >> 5;
    const int lane = tid & 31;
    const float* f = (t == 0 ? mf1 : mf2) + ((size_t)b * E_ + e) * HW_ + hw0;

    float s1[N_], s2[N_];
    int   c[N_];
#pragma unroll
    for (int n = 0; n < N_; n++) { s1[n] = 0.f; s2[n] = 0.f; c[n] = 0; }

    for (int k = lane; k < CPIX; k += 32) {
        float x  = f[k];
        float x2 = x * x;
        unsigned pw = spack[k];
#pragma unroll
        for (int n = 0; n < N_; n++) {
            if ((pw >> n) & 1u) { s1[n] += x; s2[n] += x2; c[n]++; }
        }
    }

#pragma unroll
    for (int n = 0; n < N_; n++) {
        float a  = s1[n];
        float bb = s2[n];
        for (int off = 16; off; off >>= 1) {
            a  += __shfl_down_sync(0xffffffffu, a,  off);
            bb += __shfl_down_sync(0xffffffffu, bb, off);
        }
        if (lane == 0) {
            atomicAdd(&d_S1[((size_t)b * N_ + n) * E_ + e], (double)a);
            atomicAdd(&d_S2[((size_t)b * N_ + n) * E_ + e], (double)bb);
        }
    }
    if (e == 0) {
#pragma unroll
        for (int n = 0; n < N_; n++) {
            int cc = c[n];
            for (int off = 16; off; off >>= 1)
                cc += __shfl_down_sync(0xffffffffu, cc, off);
            if (lane == 0) atomicAdd(&d_cnt[b * N_ + n], (unsigned)cc);
        }
    }

    // Fused finalize (last block)
    __threadfence();
    __shared__ bool isLast;
    if (tid == 0) isLast = (atomicAdd(&d_tick1, 1u) == (unsigned)(64 * B_ - 1));
    __syncthreads();
    if (isLast && tid < BN_ * E_) {
        int inst   = tid / E_;
        double cnt = (double)d_cnt[inst];
        double s1v = d_S1[tid];
        double s2v = d_S2[tid];
        double mean = s1v / cnt;
        double var  = (s2v - s1v * s1v / cnt) / (cnt - 1.0);
        d_mean[tid] = (float)mean;
        d_nhv[tid]  = (float)(-0.5 * var);
    }
}

// ---------------------------------------------------------------------------
// Kernel 2: per-pixel distance -> error -> histogram (warp-aggregated atomics)
// grid 720, block 256. One thread = one pixel (covers both batches).
// ---------------------------------------------------------------------------
__global__ void __launch_bounds__(256) k_hist(const float* __restrict__ mf1,
                                              const float* __restrict__ mf2) {
    __shared__ float sm_mean[NE_];
    __shared__ float sm_nhv [NE_];
    const int tid = threadIdx.x;
    const int b   = (blockIdx.x * 256) / P_;         // uniform in block (P_ % 256 == 0)
    if (tid < NE_) {
        sm_mean[tid] = d_mean[b * NE_ + tid];
        sm_nhv [tid] = d_nhv [b * NE_ + tid];
    }
    __syncthreads();

    const int pp = blockIdx.x * 256 + tid;           // < B_*P_ exactly
    const int p  = pp - b * P_;
    const int t  = p / HW_;
    const int hw = p - t * HW_;
    const int lane = tid & 31;

    const float* f = (t == 0 ? mf1 : mf2) + (size_t)b * E_ * HW_ + hw;
    float x[E_];
#pragma unroll
    for (int e = 0; e < E_; e++) x[e] = f[(size_t)e * HW_];

    const unsigned pw = d_pack[pp];

#pragma unroll
    for (int n = 0; n < N_; n++) {
        float d = 0.f;
#pragma unroll
        for (int e = 0; e < E_; e++) {
            float diff = x[e] - sm_mean[n * E_ + e];
            d = fmaf(diff * diff, sm_nhv[n * E_ + e], d);  // d = -0.5 * sum
        }
        float q   = __expf(d);                       // in (0, 1]
        unsigned mv = (pw >> n) & 1u;
        float err = mv ? (2.0f - 2.0f * q) : (2.0f * q);
        int bin   = (int)(err * BIN_SCALE);
        bin       = bin < (NBINS - 1) ? bin : (NBINS - 1);

        // warp-aggregate identical (mv, bin) pairs -> one atomic per group
        unsigned key   = (mv << 14) | (unsigned)bin;
        unsigned peers = __match_any_sync(0xffffffffu, key);
        int leader     = __ffs(peers) - 1;
        if (lane == leader) {
            int slot = ((b * N_ + n) << 1) | (int)mv;
            atomicAdd(&d_hist[(size_t)slot * NBINS + bin],
                      (unsigned)__popc(peers));
        }
    }
}

// ---------------------------------------------------------------------------
// Kernel 3: histogram scan + Lovasz via exact int64 rational + fp32 divide.
// One block per instance; 1024 threads x 16 bins.  Also zeroes the histogram
// bins it read and (last block) resets all accumulators + writes the output.
//   Descending-error order; runP/runN = ascending exclusive prefixes.
//   cp1 = gts - runP, cn1 = totNeg - runN  (J1 operands)
//   dJ  = num/den,  num = gts*(cp+cn) + cp*cn1 - cp1*cn   (exact int64)
//   den = (gts + cn1 - cn) * (gts + cn1)                  (exact int64)
// ---------------------------------------------------------------------------
__global__ void __launch_bounds__(1024) k_loss(float* __restrict__ out) {
    const int inst = blockIdx.x;
    const int tid  = threadIdx.x;
    const int lane = tid & 31;
    const int wid  = tid >> 5;
    const size_t baseN = ((size_t)(inst * 2)     * NBINS) + (size_t)tid * BPT;
    const size_t baseP = ((size_t)(inst * 2 + 1) * NBINS) + (size_t)tid * BPT;

    unsigned cntP[BPT], cntN[BPT];
    const uint4 z4 = make_uint4(0u, 0u, 0u, 0u);
#pragma unroll
    for (int j = 0; j < BPT; j += 4) {
        uint4 vp = *reinterpret_cast<const uint4*>(&d_hist[baseP + j]);
        uint4 vn = *reinterpret_cast<const uint4*>(&d_hist[baseN + j]);
        cntP[j] = vp.x; cntP[j+1] = vp.y; cntP[j+2] = vp.z; cntP[j+3] = vp.w;
        cntN[j] = vn.x; cntN[j+1] = vn.y; cntN[j+2] = vn.z; cntN[j+3] = vn.w;
        *reinterpret_cast<uint4*>(&d_hist[baseP + j]) = z4;   // self-clean
        *reinterpret_cast<uint4*>(&d_hist[baseN + j]) = z4;
    }
    unsigned tp = 0, tn = 0;
#pragma unroll
    for (int j = 0; j < BPT; j++) { tp += cntP[j]; tn += cntN[j]; }

    // block-wide exclusive scan: warp shuffle scan + cross-warp scan
    __shared__ unsigned swp[32], swn[32];
    unsigned ip = tp, inn = tn;
#pragma unroll
    for (int o = 1; o < 32; o <<= 1) {
        unsigned a = __shfl_up_sync(0xffffffffu, ip,  o);
        unsigned c = __shfl_up_sync(0xffffffffu, inn, o);
        if (lane >= o) { ip += a; inn += c; }
    }
    if (lane == 31) { swp[wid] = ip; swn[wid] = inn; }
    __syncthreads();
    if (wid == 0) {
        unsigned op = swp[lane], on = swn[lane];
        unsigned a = op, c = on;
#pragma unroll
        for (int o = 1; o < 32; o <<= 1) {
            unsigned xa = __shfl_up_sync(0xffffffffu, a, o);
            unsigned xc = __shfl_up_sync(0xffffffffu, c, o);
            if (lane >= o) { a += xa; c += xc; }
        }
        swp[lane] = a - op;          // exclusive warp-total prefix
        swn[lane] = c - on;
    }
    __syncthreads();
    const unsigned runP0 = swp[wid] + (ip - tp);
    const unsigned runN0 = swn[wid] + (inn - tn);

    const long long gts    = (long long)d_cnt[inst];
    const long long totNeg = (long long)P_ - gts;
    long long cp1 = gts    - (long long)runP0;
    long long cn1 = totNeg - (long long)runN0;

    float acc = 0.f;
#pragma unroll
    for (int j = 0; j < BPT; j++) {
        const unsigned cp = cntP[j], cn = cntN[j];
        if (cp | cn) {
            long long num = gts * (long long)(cp + cn)
                          + (long long)cp * cn1 - cp1 * (long long)cn;
            long long den = (gts + cn1 - (long long)cn) * (gts + cn1);
            float e_rep = ((float)(tid * BPT + j) + 0.5f) * DBINF;
            acc += e_rep * ((float)num / (float)den);
        }
        cp1 -= (long long)cp;
        cn1 -= (long long)cn;
    }

    // block reduce (double)
    __shared__ double dw[32];
    double dacc = (double)acc;
#pragma unroll
    for (int o = 16; o; o >>= 1)
        dacc += __shfl_down_sync(0xffffffffu, dacc, o);
    if (lane == 0) dw[wid] = dacc;
    __syncthreads();
    if (wid == 0) {
        double v = dw[lane];
#pragma unroll
        for (int o = 16; o; o >>= 1)
            v += __shfl_down_sync(0xffffffffu, v, o);
        if (lane == 0) atomicAdd(&d_total, v);
    }

    // last block: write scalar output, then reset all state to zero
    __threadfence();
    __shared__ bool isLast;
    if (tid == 0) isLast = (atomicAdd(&d_tick2, 1u) == (unsigned)(BN_ - 1));
    __syncthreads();
    if (isLast) {
        if (tid == 0) {
            out[0] = (float)(d_total / (double)BN_);
            d_total = 0.0;
            d_tick1 = 0u;
            d_tick2 = 0u;
        }
        if (tid < BN_ * E_) { d_S1[tid] = 0.0; d_S2[tid] = 0.0; }
        if (tid < BN_)      { d_cnt[tid] = 0u; }
    }
}

extern "C" void kernel_launch(void* const* d_in, const int* in_sizes, int n_in,
                              void* d_out, int out_size) {
    const float* mf1 = (const float*)d_in[0];
    const float* mf2 = (const float*)d_in[1];
    const int*   gt  = (const int*)d_in[2];

    k_stats<<<dim3(64, B_), 512>>>(mf1, mf2, gt);
    k_hist<<<(B_ * P_) / 256, 256>>>(mf1, mf2);
    k_loss<<<BN_, 1024>>>((float*)d_out);
}